// round 16
// baseline (speedup 1.0000x reference)
#include <cuda_runtime.h>
#include <cuda_bf16.h>
#include <math.h>
#include <stdint.h>

#define B 4
#define C 128
#define N 4096
#define TPB 256

// ---------------------------------------------------------------------------
// Scratch (device globals)
// ---------------------------------------------------------------------------
__device__ __align__(16) __nv_bfloat16 g_xth[B*N*C]; // x transposed token-major hi
__device__ __align__(16) __nv_bfloat16 g_xtl[B*N*C]; // x transposed token-major lo
__device__ __align__(16) __nv_bfloat16 g_wth[4*C*C]; // W hi, natural [o][c]
__device__ __align__(16) __nv_bfloat16 g_wtl[4*C*C]; // W lo
__device__ __align__(16) __nv_bfloat16 g_qh[B*N*C];  // token-major (b,n,c) hi
__device__ __align__(16) __nv_bfloat16 g_ql[B*N*C];
__device__ __align__(16) __nv_bfloat16 g_kh[B*N*C];
__device__ __align__(16) __nv_bfloat16 g_kl[B*N*C];
__device__ __align__(16) __nv_bfloat16 g_vh[B*C*N];  // channel-major (b,c,n) hi
__device__ __align__(16) __nv_bfloat16 g_vl[B*C*N];
__device__ float g_a2[2*B*C*N];                       // partial attn out (token-major)
__device__ float g_l[2*B*N];                          // partial softmax denominators

// ---------------------------------------------------------------------------
// helpers
// ---------------------------------------------------------------------------
__device__ __forceinline__ uint32_t s2u(const void* p) {
    return (uint32_t)__cvta_generic_to_shared(p);
}
__device__ __forceinline__ void ldsm4(uint32_t r[4], uint32_t addr) {
    asm volatile("ldmatrix.sync.aligned.m8n8.x4.shared.b16 {%0,%1,%2,%3}, [%4];"
                 : "=r"(r[0]), "=r"(r[1]), "=r"(r[2]), "=r"(r[3]) : "r"(addr));
}
__device__ __forceinline__ void mma16816(float d[4], const uint32_t a[4],
                                         uint32_t b0, uint32_t b1) {
    asm("mma.sync.aligned.m16n8k16.row.col.f32.bf16.bf16.f32 "
        "{%0,%1,%2,%3}, {%4,%5,%6,%7}, {%8,%9}, {%0,%1,%2,%3};"
        : "+f"(d[0]), "+f"(d[1]), "+f"(d[2]), "+f"(d[3])
        : "r"(a[0]), "r"(a[1]), "r"(a[2]), "r"(a[3]), "r"(b0), "r"(b1));
}
__device__ __forceinline__ void split1(float x, __nv_bfloat16& h, __nv_bfloat16& l) {
    h = __float2bfloat16(x);
    l = __float2bfloat16(x - __bfloat162float(h));
}
__device__ __forceinline__ void pack2(float x, float y, uint32_t& h, uint32_t& l) {
    __nv_bfloat16 hx, lx, hy, ly;
    split1(x, hx, lx); split1(y, hy, ly);
    h = (uint32_t)__bfloat16_as_ushort(hx) | ((uint32_t)__bfloat16_as_ushort(hy) << 16);
    l = (uint32_t)__bfloat16_as_ushort(lx) | ((uint32_t)__bfloat16_as_ushort(ly) << 16);
}
__device__ __forceinline__ void cpa16(uint32_t d, const void* s) {
    asm volatile("cp.async.cg.shared.global [%0], [%1], 16;" :: "r"(d), "l"(s));
}
#define CP_COMMIT() asm volatile("cp.async.commit_group;" ::)
#define CP_WAIT(n)  asm volatile("cp.async.wait_group %0;" :: "n"(n))

// ---------------------------------------------------------------------------
// Kernel A: transpose x to token-major bf16 hi/lo
// ---------------------------------------------------------------------------
__global__ __launch_bounds__(TPB) void trans_kernel(const float* __restrict__ x) {
    __shared__ float t[64][65];
    int i0 = blockIdx.x * 64, c0 = blockIdx.y * 64, b = blockIdx.z;
    int tid = threadIdx.x;
#pragma unroll
    for (int r = 0; r < 4; r++) {
        int idx = tid + TPB*r;
        int c = idx >> 4, i4 = idx & 15;
        float4 v = *(const float4*)(x + (size_t)(b*C + c0 + c)*N + i0 + i4*4);
        t[c][i4*4+0] = v.x; t[c][i4*4+1] = v.y; t[c][i4*4+2] = v.z; t[c][i4*4+3] = v.w;
    }
    __syncthreads();
#pragma unroll
    for (int r = 0; r < 2; r++) {
        int idx = tid + TPB*r;
        int i = idx >> 3, ch = idx & 7;
        __align__(16) __nv_bfloat16 hb[8], lb[8];
#pragma unroll
        for (int k = 0; k < 8; k++) split1(t[ch*8+k][i], hb[k], lb[k]);
        size_t base = (size_t)(b*N + i0 + i)*C + c0 + ch*8;
        *(uint4*)(g_xth + base) = *(uint4*)hb;
        *(uint4*)(g_xtl + base) = *(uint4*)lb;
    }
}

// ---------------------------------------------------------------------------
// Kernel 0: split weights to bf16 hi/lo
// ---------------------------------------------------------------------------
__global__ void wt_kernel(const float* __restrict__ Wq, const float* __restrict__ Wk,
                          const float* __restrict__ Wv, const float* __restrict__ Wo) {
    int w = blockIdx.x;
    const float* src = (w == 0) ? Wq : (w == 1) ? Wk : (w == 2) ? Wv : Wo;
    for (int idx = threadIdx.x; idx < C*C; idx += blockDim.x) {
        __nv_bfloat16 h, l;
        split1(src[idx], h, l);
        g_wth[w*C*C + idx] = h;
        g_wtl[w*C*C + idx] = l;
    }
}

// ---------------------------------------------------------------------------
// Shared mma-GEMM geometry for qkv / out kernels
// ---------------------------------------------------------------------------
#define PADT 136
#define E_AH 0
#define E_AL 17408
#define E_BH 34816
#define E_BL 52224
#define SMEM_MMA (69632*2 + 512)

// ---------------------------------------------------------------------------
// Kernel 1: QKV conv via bf16-split mma. grid (N/128, 3, B)
// ---------------------------------------------------------------------------
__global__ __launch_bounds__(TPB) void qkv_kernel(const float* __restrict__ bq,
        const float* __restrict__ bk, const float* __restrict__ bv) {
    extern __shared__ __align__(16) __nv_bfloat16 smb[];
    uint32_t smu = s2u(smb);
    float* bias_s = (float*)((char*)smb + 69632*2);
    int i0 = blockIdx.x * 128, mode = blockIdx.y, b = blockIdx.z;
    int tid = threadIdx.x, wid = tid >> 5, lane = tid & 31;
    int gid = lane >> 2, tig = lane & 3;
    int qw = wid * 16;

#pragma unroll
    for (int r = 0; r < 8; r++) {
        int idx = tid + TPB*r;
        int row = idx >> 4, c16 = idx & 15;
        size_t gb = (size_t)(b*N + i0 + row)*C + c16*8;
        *(uint4*)(smb + E_AH + row*PADT + c16*8) = *(const uint4*)(g_xth + gb);
        *(uint4*)(smb + E_AL + row*PADT + c16*8) = *(const uint4*)(g_xtl + gb);
        size_t wb = (size_t)mode*C*C + row*C + c16*8;
        *(uint4*)(smb + E_BH + row*PADT + c16*8) = *(const uint4*)(g_wth + wb);
        *(uint4*)(smb + E_BL + row*PADT + c16*8) = *(const uint4*)(g_wtl + wb);
    }
    const float* bias = (mode == 0) ? bq : (mode == 1) ? bk : bv;
    if (tid < 128) bias_s[tid] = bias[tid];
    __syncthreads();

    uint32_t offA = (uint32_t)((qw + (lane & 15))*PADT + ((lane >> 4) << 3)) * 2;
    int rowB = (lane & 7) + ((lane >> 4) << 3);
    int colB = ((lane >> 3) & 1) << 3;

    float D[8][2][4];
#pragma unroll
    for (int nb = 0; nb < 8; nb++)
#pragma unroll
        for (int f = 0; f < 2; f++) {
            float b0 = bias_s[nb*16 + f*8 + tig*2];
            float b1 = bias_s[nb*16 + f*8 + tig*2 + 1];
            D[nb][f][0] = b0; D[nb][f][1] = b1; D[nb][f][2] = b0; D[nb][f][3] = b1;
        }

#pragma unroll
    for (int kk = 0; kk < 8; kk++) {
        uint32_t ah[4], al[4];
        ldsm4(ah, smu + E_AH*2 + offA + kk*32);
        ldsm4(al, smu + E_AL*2 + offA + kk*32);
#pragma unroll
        for (int nb = 0; nb < 8; nb++) {
            uint32_t bh[4], bl[4];
            uint32_t boff = (uint32_t)((nb*16 + rowB)*PADT + kk*16 + colB) * 2;
            ldsm4(bh, smu + E_BH*2 + boff);
            ldsm4(bl, smu + E_BL*2 + boff);
            mma16816(D[nb][0], ah, bh[0], bh[1]);
            mma16816(D[nb][1], ah, bh[2], bh[3]);
            mma16816(D[nb][0], ah, bl[0], bl[1]);
            mma16816(D[nb][1], ah, bl[2], bl[3]);
            mma16816(D[nb][0], al, bh[0], bh[1]);
            mma16816(D[nb][1], al, bh[2], bh[3]);
        }
    }

    if (mode < 2) {
        __nv_bfloat16* dh = mode ? g_kh : g_qh;
        __nv_bfloat16* dl = mode ? g_kl : g_ql;
        int i = i0 + qw + gid;
#pragma unroll
        for (int nb = 0; nb < 8; nb++)
#pragma unroll
            for (int f = 0; f < 2; f++) {
                int o = nb*16 + f*8 + tig*2;
                uint32_t h, l;
                pack2(D[nb][f][0], D[nb][f][1], h, l);
                size_t p0 = (size_t)(b*N + i)*C + o;
                *(uint32_t*)(dh + p0) = h;
                *(uint32_t*)(dl + p0) = l;
                pack2(D[nb][f][2], D[nb][f][3], h, l);
                size_t p1 = (size_t)(b*N + i + 8)*C + o;
                *(uint32_t*)(dh + p1) = h;
                *(uint32_t*)(dl + p1) = l;
            }
    } else {
        __syncthreads();
        float* st = (float*)smb;
#pragma unroll
        for (int nb = 0; nb < 8; nb++)
#pragma unroll
            for (int f = 0; f < 2; f++) {
                int o = nb*16 + f*8 + tig*2;
                int il = qw + gid;
                st[o*132 + il]           = D[nb][f][0];
                st[(o+1)*132 + il]       = D[nb][f][1];
                st[o*132 + il + 8]       = D[nb][f][2];
                st[(o+1)*132 + il + 8]   = D[nb][f][3];
            }
        __syncthreads();
#pragma unroll
        for (int r = 0; r < 8; r++) {
            int idx = tid + TPB*r;
            int o = idx >> 4, ch = idx & 15;
            __align__(16) __nv_bfloat16 hb[8], lb[8];
#pragma unroll
            for (int k = 0; k < 8; k++) split1(st[o*132 + ch*8 + k], hb[k], lb[k]);
            size_t base = (size_t)(b*C + o)*N + i0 + ch*8;
            *(uint4*)(g_vh + base) = *(uint4*)hb;
            *(uint4*)(g_vl + base) = *(uint4*)lb;
        }
    }
}

// ---------------------------------------------------------------------------
// Kernel 2: flash attention — QT=128, 2 CTAs/SM, single KV buffer (KT=32),
// split-K across 2 CTAs, no-max softmax.
// grid (N/128, 2, B) = 256 CTAs.
// ---------------------------------------------------------------------------
#define PADQ 136
#define PADV 40
#define KT   32
#define QT   128

// smem element offsets
#define A_QH 0
#define A_QL 17408
#define A_K(hl) (34816 + (hl)*4352)
#define A_V(hl) (43520 + (hl)*5120)
#define SMEM_ATTN 107520   // bytes = 53760 elems * 2

__device__ __forceinline__ void load_kv(uint32_t smbu, int b, int k0, int tid) {
#pragma unroll
    for (int r = 0; r < 4; r++) {          // K: 1024 x 16B (hi+lo)
        int idx = tid + TPB*r;
        int hl = idx >> 9, rem = idx & 511;
        int row = rem >> 4, c16 = rem & 15;
        const __nv_bfloat16* src = (hl ? g_kl : g_kh) + (size_t)(b*N + k0 + row)*C + c16*8;
        cpa16(smbu + (A_K(hl) + row*PADQ + c16*8)*2, src);
    }
#pragma unroll
    for (int r = 0; r < 4; r++) {          // V: 1024 x 16B (hi+lo)
        int idx = tid + TPB*r;
        int hl = idx >> 9, rem = idx & 511;
        int row = rem >> 2, j8 = rem & 3;
        const __nv_bfloat16* src = (hl ? g_vl : g_vh) + (size_t)(b*C + row)*N + k0 + j8*8;
        cpa16(smbu + (A_V(hl) + row*PADV + j8*8)*2, src);
    }
}

__global__ __launch_bounds__(TPB, 2) void attn_kernel() {
    extern __shared__ __align__(16) __nv_bfloat16 smbuf[];
    uint32_t smbu = s2u(smbuf);
    int q0 = blockIdx.x * QT, kh = blockIdx.y, b = blockIdx.z;
    int tid = threadIdx.x, wid = tid >> 5, lane = tid & 31;
    int gid = lane >> 2, tig = lane & 3;
    int qw = wid * 16;
    int kbase = kh * (N/2);

    // prologue: Q tile (hi+lo) + first KV tile
#pragma unroll
    for (int r = 0; r < 16; r++) {         // Q: 4096 x 16B
        int idx = tid + TPB*r;
        int hl = idx >> 11, rem = idx & 2047;
        int row = rem >> 4, c16 = rem & 15;
        const __nv_bfloat16* src = (hl ? g_ql : g_qh) + (size_t)(b*N + q0 + row)*C + c16*8;
        cpa16(smbu + ((hl ? A_QL : A_QH) + row*PADQ + c16*8)*2, src);
    }
    load_kv(smbu, b, kbase, tid);
    CP_COMMIT();

    int colA = (lane >> 4) << 3;
    uint32_t offA = (uint32_t)((qw + (lane & 15))*PADQ + colA) * 2;
    int rowB = (lane & 7) + ((lane >> 4) << 3);
    int colB = ((lane >> 3) & 1) << 3;

    float O[16][4];
#pragma unroll
    for (int cn = 0; cn < 16; cn++)
#pragma unroll
        for (int e = 0; e < 4; e++) O[cn][e] = 0.f;
    float lp0 = 0.f, lp1 = 0.f;

    const int NB = (N/2) / KT;             // 64 iterations
    for (int it = 0; it < NB; it++) {
        CP_WAIT(0);
        __syncthreads();

        uint32_t cKh = smbu + A_K(0)*2, cKl = smbu + A_K(1)*2;
        uint32_t cVh = smbu + A_V(0)*2, cVl = smbu + A_V(1)*2;

        // ---- S = Q^T K : 16q x 32j per warp ----
        float S[4][4];
#pragma unroll
        for (int nf = 0; nf < 4; nf++)
#pragma unroll
            for (int e = 0; e < 4; e++) S[nf][e] = 0.f;

#pragma unroll
        for (int kk = 0; kk < 8; kk++) {
            uint32_t qhf[4], qlf[4];
            ldsm4(qhf, smbu + A_QH*2 + offA + kk*32);
            ldsm4(qlf, smbu + A_QL*2 + offA + kk*32);
            uint32_t bh0[4], bl0[4], bh1[4], bl1[4];
            uint32_t boff0 = (uint32_t)((rowB)*PADQ + kk*16 + colB) * 2;
            uint32_t boff1 = (uint32_t)((16 + rowB)*PADQ + kk*16 + colB) * 2;
            ldsm4(bh0, cKh + boff0);
            ldsm4(bl0, cKl + boff0);
            ldsm4(bh1, cKh + boff1);
            ldsm4(bl1, cKl + boff1);
            mma16816(S[0], qhf, bh0[0], bh0[1]);
            mma16816(S[1], qhf, bh0[2], bh0[3]);
            mma16816(S[2], qhf, bh1[0], bh1[1]);
            mma16816(S[3], qhf, bh1[2], bh1[3]);
            mma16816(S[0], qhf, bl0[0], bl0[1]);
            mma16816(S[1], qhf, bl0[2], bl0[3]);
            mma16816(S[2], qhf, bl1[0], bl1[1]);
            mma16816(S[3], qhf, bl1[2], bl1[3]);
            mma16816(S[0], qlf, bh0[0], bh0[1]);
            mma16816(S[1], qlf, bh0[2], bh0[3]);
            mma16816(S[2], qlf, bh1[0], bh1[1]);
            mma16816(S[3], qlf, bh1[2], bh1[3]);
        }

        // ---- no-max softmax ----
        uint32_t PH[2][4], PL[2][4];
#pragma unroll
        for (int nf = 0; nf < 4; nf++) {
            S[nf][0] = __expf(S[nf][0]);
            S[nf][1] = __expf(S[nf][1]);
            S[nf][2] = __expf(S[nf][2]);
            S[nf][3] = __expf(S[nf][3]);
            lp0 += S[nf][0] + S[nf][1];
            lp1 += S[nf][2] + S[nf][3];
        }
#pragma unroll
        for (int kg = 0; kg < 2; kg++) {
            pack2(S[2*kg][0],   S[2*kg][1],   PH[kg][0], PL[kg][0]);
            pack2(S[2*kg][2],   S[2*kg][3],   PH[kg][1], PL[kg][1]);
            pack2(S[2*kg+1][0], S[2*kg+1][1], PH[kg][2], PL[kg][2]);
            pack2(S[2*kg+1][2], S[2*kg+1][3], PH[kg][3], PL[kg][3]);
        }

        // ---- O += P V ----
#pragma unroll
        for (int kg = 0; kg < 2; kg++) {
#pragma unroll
            for (int cn2 = 0; cn2 < 8; cn2++) {
                uint32_t vh[4], vl[4];
                uint32_t voff = (uint32_t)((cn2*16 + rowB)*PADV + kg*16 + colB) * 2;
                ldsm4(vh, cVh + voff);
                ldsm4(vl, cVl + voff);
                mma16816(O[2*cn2],   PH[kg], vh[0], vh[1]);
                mma16816(O[2*cn2+1], PH[kg], vh[2], vh[3]);
                mma16816(O[2*cn2],   PH[kg], vl[0], vl[1]);
                mma16816(O[2*cn2+1], PH[kg], vl[2], vl[3]);
                mma16816(O[2*cn2],   PL[kg], vh[0], vh[1]);
                mma16816(O[2*cn2+1], PL[kg], vh[2], vh[3]);
            }
        }
        __syncthreads();
        if (it + 1 < NB) {
            load_kv(smbu, b, kbase + (it+1)*KT, tid);
            CP_COMMIT();
        }
    }

    // epilogue: write partial O token-major + partial l
    size_t half_off = (size_t)kh * ((size_t)B*C*N);
    int qr0 = q0 + qw + gid;
#pragma unroll
    for (int cn = 0; cn < 16; cn++) {
        int c = cn*8 + tig*2;
        size_t rb0 = half_off + (size_t)(b*N + qr0)*C + c;
        size_t rb1 = half_off + (size_t)(b*N + qr0 + 8)*C + c;
        *(float2*)(g_a2 + rb0) = make_float2(O[cn][0], O[cn][1]);
        *(float2*)(g_a2 + rb1) = make_float2(O[cn][2], O[cn][3]);
    }
    float v0 = lp0;
    v0 += __shfl_xor_sync(0xffffffffu, v0, 1);
    v0 += __shfl_xor_sync(0xffffffffu, v0, 2);
    float v1 = lp1;
    v1 += __shfl_xor_sync(0xffffffffu, v1, 1);
    v1 += __shfl_xor_sync(0xffffffffu, v1, 2);
    if (tig == 0) {
        g_l[kh*(B*N) + b*N + qr0]     = v0;
        g_l[kh*(B*N) + b*N + qr0 + 8] = v1;
    }
}

// ---------------------------------------------------------------------------
// Kernel 3: combine + normalize + output conv (mma) + bias + residual
// ---------------------------------------------------------------------------
__global__ __launch_bounds__(TPB) void out_kernel(const float* __restrict__ x,
        const float* __restrict__ bo, float* __restrict__ out) {
    extern __shared__ __align__(16) __nv_bfloat16 smb[];
    uint32_t smu = s2u(smb);
    float* bias_s = (float*)((char*)smb + 69632*2);
    int i0 = blockIdx.x * 128, b = blockIdx.y;
    int tid = threadIdx.x, wid = tid >> 5, lane = tid & 31;
    int gid = lane >> 2, tig = lane & 3;
    int qw = wid * 16;
    const size_t BCN = (size_t)B*C*N;

#pragma unroll
    for (int r = 0; r < 16; r++) {
        int idx = tid + TPB*r;
        int i = idx >> 5, c4 = idx & 31;
        size_t rb = (size_t)(b*N + i0 + i)*C + c4*4;
        float4 a0 = *(const float4*)(g_a2 + rb);
        float4 a1 = *(const float4*)(g_a2 + BCN + rb);
        float inv = 1.f / (g_l[b*N + i0 + i] + g_l[B*N + b*N + i0 + i]);
        float v[4] = {(a0.x+a1.x)*inv, (a0.y+a1.y)*inv, (a0.z+a1.z)*inv, (a0.w+a1.w)*inv};
#pragma unroll
        for (int k = 0; k < 4; k++) {
            __nv_bfloat16 h, l;
            split1(v[k], h, l);
            smb[E_AH + i*PADT + c4*4 + k] = h;
            smb[E_AL + i*PADT + c4*4 + k] = l;
        }
    }
#pragma unroll
    for (int r = 0; r < 8; r++) {
        int idx = tid + TPB*r;
        int row = idx >> 4, c16 = idx & 15;
        size_t wb = (size_t)3*C*C + row*C + c16*8;
        *(uint4*)(smb + E_BH + row*PADT + c16*8) = *(const uint4*)(g_wth + wb);
        *(uint4*)(smb + E_BL + row*PADT + c16*8) = *(const uint4*)(g_wtl + wb);
    }
    if (tid < 128) bias_s[tid] = bo[tid];
    __syncthreads();

    uint32_t offA = (uint32_t)((qw + (lane & 15))*PADT + ((lane >> 4) << 3)) * 2;
    int rowB = (lane & 7) + ((lane >> 4) << 3);
    int colB = ((lane >> 3) & 1) << 3;

    float D[8][2][4];
#pragma unroll
    for (int nb = 0; nb < 8; nb++)
#pragma unroll
        for (int f = 0; f < 2; f++) {
            float b0 = bias_s[nb*16 + f*8 + tig*2];
            float b1 = bias_s[nb*16 + f*8 + tig*2 + 1];
            D[nb][f][0] = b0; D[nb][f][1] = b1; D[nb][f][2] = b0; D[nb][f][3] = b1;
        }

#pragma unroll
    for (int kk = 0; kk < 8; kk++) {
        uint32_t ah[4], al[4];
        ldsm4(ah, smu + E_AH*2 + offA + kk*32);
        ldsm4(al, smu + E_AL*2 + offA + kk*32);
#pragma unroll
        for (int nb = 0; nb < 8; nb++) {
            uint32_t bh[4], bl[4];
            uint32_t boff = (uint32_t)((nb*16 + rowB)*PADT + kk*16 + colB) * 2;
            ldsm4(bh, smu + E_BH*2 + boff);
            ldsm4(bl, smu + E_BL*2 + boff);
            mma16816(D[nb][0], ah, bh[0], bh[1]);
            mma16816(D[nb][1], ah, bh[2], bh[3]);
            mma16816(D[nb][0], ah, bl[0], bl[1]);
            mma16816(D[nb][1], ah, bl[2], bl[3]);
            mma16816(D[nb][0], al, bh[0], bh[1]);
            mma16816(D[nb][1], al, bh[2], bh[3]);
        }
    }

    __syncthreads();
    float* st = (float*)smb;
#pragma unroll
    for (int nb = 0; nb < 8; nb++)
#pragma unroll
        for (int f = 0; f < 2; f++) {
            int o = nb*16 + f*8 + tig*2;
            int il = qw + gid;
            st[o*132 + il]         = D[nb][f][0];
            st[(o+1)*132 + il]     = D[nb][f][1];
            st[o*132 + il + 8]     = D[nb][f][2];
            st[(o+1)*132 + il + 8] = D[nb][f][3];
        }
    __syncthreads();
#pragma unroll
    for (int r = 0; r < 16; r++) {
        int idx = tid + TPB*r;
        int o = idx >> 5, i4 = idx & 31;
        size_t base = (size_t)(b*C + o)*N + i0 + i4*4;
        float4 xv = *(const float4*)(x + base);
        *(float4*)(out + base) = make_float4(
            st[o*132 + i4*4 + 0] + xv.x, st[o*132 + i4*4 + 1] + xv.y,
            st[o*132 + i4*4 + 2] + xv.z, st[o*132 + i4*4 + 3] + xv.w);
    }
}

// ---------------------------------------------------------------------------
extern "C" void kernel_launch(void* const* d_in, const int* in_sizes, int n_in,
                              void* d_out, int out_size) {
    const float* x  = (const float*)d_in[0];
    const float* Wq = (const float*)d_in[1];
    const float* bq = (const float*)d_in[2];
    const float* Wk = (const float*)d_in[3];
    const float* bk = (const float*)d_in[4];
    const float* Wv = (const float*)d_in[5];
    const float* bv = (const float*)d_in[6];
    const float* Wo = (const float*)d_in[7];
    const float* bo = (const float*)d_in[8];
    float* out = (float*)d_out;

    cudaFuncSetAttribute(qkv_kernel,  cudaFuncAttributeMaxDynamicSharedMemorySize, SMEM_MMA);
    cudaFuncSetAttribute(attn_kernel, cudaFuncAttributeMaxDynamicSharedMemorySize, SMEM_ATTN);
    cudaFuncSetAttribute(out_kernel,  cudaFuncAttributeMaxDynamicSharedMemorySize, SMEM_MMA);

    trans_kernel<<<dim3(N/64, C/64, B), TPB>>>(x);
    wt_kernel<<<4, 256>>>(Wq, Wk, Wv, Wo);
    qkv_kernel<<<dim3(N/128, 3, B), TPB, SMEM_MMA>>>(bq, bk, bv);
    attn_kernel<<<dim3(N/QT, 2, B), TPB, SMEM_ATTN>>>();
    out_kernel<<<dim3(N/128, B), TPB, SMEM_MMA>>>(x, bo, out);
}